// round 2
// baseline (speedup 1.0000x reference)
#include <cuda_runtime.h>

#define NWARP 2      // warps per block
#define NB 8         // batch elements per warp
#define L 64
#define C 7
#define H 32
#define NSTEPS 126   // (L-1)*K, K=2, h = 0.5

typedef unsigned long long ull;

// ---- packed dual-fp32 FMA (sm_10x) ----
__device__ __forceinline__ ull ffma2(ull a, ull b, ull c) {
    ull d;
    asm("fma.rn.f32x2 %0, %1, %2, %3;" : "=l"(d) : "l"(a), "l"(b), "l"(c));
    return d;
}
__device__ __forceinline__ ull pk2(float x, float y) {
    ull r;
    asm("mov.b64 %0, {%1, %2};" : "=l"(r) : "f"(x), "f"(y));
    return r;
}
__device__ __forceinline__ void upk2(ull v, float &x, float &y) {
    asm("mov.b64 {%0, %1}, %2;" : "=f"(x), "=f"(y) : "l"(v));
}

// stable softplus: max(x,0) + log(1+exp(-|x|)); abs err ~1e-7
__device__ __forceinline__ float sp_(float x) {
    return fmaxf(x, 0.f) + __logf(1.f + __expf(-fabsf(x)));
}
// HW tanh approx (sm_75+), ~1e-5 abs err — tolerance budget is 1e-3, current headroom 8e-7
__device__ __forceinline__ float tanh_(float x) {
    float y;
    asm("tanh.approx.f32 %0, %1;" : "=f"(y) : "f"(x));
    return y;
}

// cubic Hermite derivative: dX = m0 + (diff-m0)*f*(4-3f)
__device__ __forceinline__ float spline_eval(const float* __restrict__ xrow, float t) {
    int idx = (int)t;
    idx = min(idx, L - 2);
    float f = t - (float)idx;
    const float* p = xrow + idx * C;
    float x0 = __ldg(p);
    float x1 = __ldg(p + C);
    float diff = x1 - x0;
    float m0 = diff;
    if (idx > 0) m0 = x0 - __ldg(p - C);
    return fmaf((diff - m0) * f, fmaf(-3.f, f, 4.f), m0);
}

__global__ __launch_bounds__(NWARP * 32)
void cde_kernel(const float* __restrict__ X,      // (4096,64,7)
                const float* __restrict__ Winit,  // (32,7)
                const float* __restrict__ binit,  // (32)
                const float* __restrict__ Wf1,    // (32,32)
                const float* __restrict__ bf1,    // (32)
                const float* __restrict__ Wf2,    // (224,32)
                const float* __restrict__ bf2,    // (224)
                const float* __restrict__ Wo1,    // (16,32)
                const float* __restrict__ bo1,    // (16)
                const float* __restrict__ Wo2,    // (3,16)
                const float* __restrict__ bo2,    // (3)
                float* __restrict__ out)          // (4096,3)
{
    // Wf2 transposed + padded: sW2[j][h*8 + c] = Wf2[h*7+c][j], c==7 -> 0
    __shared__ __align__(16) float sW2[32][256];             // 32 KB (shared by both warps)
    __shared__ __align__(16) float sZ[NWARP][NB][32];        // 2 KB
    __shared__ __align__(16) ull   sH1[NWARP][NB][32];       // 4 KB  (duplicated pairs)
    __shared__ __align__(16) float sDX[NWARP][3][NB][8];     // 1.5 KB

    const int tid = threadIdx.x;
    const int w = tid >> 5;
    const int lane = tid & 31;

    for (int i = tid; i < 32 * 256; i += NWARP * 32) {
        int j = i >> 8, hc = i & 255, h = hc >> 3, c = hc & 7;
        sW2[j][hc] = (c < C) ? Wf2[(h * C + c) * 32 + j] : 0.f;
    }
    __syncthreads();

    const int bbase = (blockIdx.x * NWARP + w) * NB;

    // per-lane constant registers (lane = h)
    ull rw1[16];
    {
        const float2* p = reinterpret_cast<const float2*>(Wf1 + lane * 32);
#pragma unroll
        for (int k = 0; k < 16; k++) { float2 v = __ldg(p + k); rw1[k] = pk2(v.x, v.y); }
    }
    const float rbf1 = __ldg(bf1 + lane);
    ull rbf2[4];
#pragma unroll
    for (int cp = 0; cp < 4; cp++) {
        int c0 = 2 * cp, c1 = 2 * cp + 1;
        float a = __ldg(bf2 + lane * C + c0);
        float b = (c1 < C) ? __ldg(bf2 + lane * C + c1) : 0.f;
        rbf2[cp] = pk2(a, b);
    }

    // dX lane mapping: 4 lanes per batch; lane handles channels dc and dc+4
    const int db = lane >> 2;        // 0..7
    const int dc = lane & 3;         // 0..3 ; second channel dc+4 (7 -> pad)
    const float* xrow0 = X + (size_t)(bbase + db) * (L * C) + dc;
    const float* xrow1 = X + (size_t)(bbase + db) * (L * C) + ((dc + 4 < C) ? dc + 4 : 0);
    const bool c1ok = (dc + 4 < C);

    // z0 = x[:,0] @ Winit^T + binit
    float z[NB];
#pragma unroll
    for (int b = 0; b < NB; b++) {
        float acc = __ldg(binit + lane);
        const float* xp = X + (size_t)(bbase + b) * (L * C);
#pragma unroll
        for (int c = 0; c < C; c++) acc = fmaf(__ldg(xp + c), __ldg(Winit + lane * C + c), acc);
        z[b] = acc;
    }

    // initial dX(t=0) -> slot 0  (idx=0, f=0 -> dX = x[1]-x[0])
    {
        float v0 = __ldg(xrow0 + C) - __ldg(xrow0);
        float v1 = c1ok ? (__ldg(xrow1 + C) - __ldg(xrow1)) : 0.f;
        sDX[w][0][db][dc] = v0;
        sDX[w][0][db][dc + 4] = v1;
    }
    __syncwarp();

    float t0 = 0.f;
#pragma unroll 1
    for (int i = 0; i < NSTEPS; i++, t0 += 0.5f) {
        // dX at t0+0.25 -> slot 2 ; dX at t0+0.5 -> slot (i+1)&1 (next step's A)
        {
            float vb0 = spline_eval(xrow0, t0 + 0.25f);
            float vc0 = spline_eval(xrow0, t0 + 0.5f);
            float vb1 = 0.f, vc1 = 0.f;
            if (c1ok) {
                vb1 = spline_eval(xrow1, t0 + 0.25f);
                vc1 = spline_eval(xrow1, t0 + 0.5f);
            }
            __syncwarp();
            sDX[w][2][db][dc] = vb0;
            sDX[w][2][db][dc + 4] = vb1;
            sDX[w][(i + 1) & 1][db][dc] = vc0;
            sDX[w][(i + 1) & 1][db][dc + 4] = vc1;
            __syncwarp();
        }
        const int slotA = i & 1;
        const int slotC = (i + 1) & 1;

        float ksum[NB], zs[NB];
#pragma unroll
        for (int b = 0; b < NB; b++) { zs[b] = z[b]; ksum[b] = 0.f; }

#pragma unroll 1
        for (int s = 0; s < 4; s++) {
            const int slot = (s == 0) ? slotA : ((s == 3) ? slotC : 2);

            // ---- vf(zs) ----
            __syncwarp();
#pragma unroll
            for (int b = 0; b < NB; b++) sZ[w][b][lane] = zs[b];
            __syncwarp();

            // mm1: h1_pre[lane] = sum_j zs[j]*Wf1[lane][j]   (packed; 128-bit z loads)
            ull a1[NB];
#pragma unroll
            for (int b = 0; b < NB; b++) a1[b] = 0ull;
#pragma unroll
            for (int k4 = 0; k4 < 8; k4++) {
#pragma unroll
                for (int b = 0; b < NB; b++) {
                    ulonglong2 zq = *reinterpret_cast<const ulonglong2*>(&sZ[w][b][4 * k4]);
                    a1[b] = ffma2(zq.x, rw1[2 * k4], a1[b]);
                    a1[b] = ffma2(zq.y, rw1[2 * k4 + 1], a1[b]);
                }
            }
            float h1[NB];
#pragma unroll
            for (int b = 0; b < NB; b++) {
                float u, v; upk2(a1[b], u, v);
                h1[b] = sp_(u + v + rbf1);
            }
            __syncwarp();
#pragma unroll
            for (int b = 0; b < NB; b++) sH1[w][b][lane] = pk2(h1[b], h1[b]);
            __syncwarp();

            // mm2: g_pre[lane*7+c] = sum_j h1[j]*Wf2[lane*7+c][j]  (c packed, j unrolled x2)
            ull a2[NB][4];
#pragma unroll
            for (int b = 0; b < NB; b++)
#pragma unroll
                for (int cp = 0; cp < 4; cp++) a2[b][cp] = rbf2[cp];

            const float* wrow = &sW2[0][lane * 8];
#pragma unroll 4
            for (int j2 = 0; j2 < 16; j2++) {
                const float* wp = wrow + (2 * j2) * 256;
                ulonglong2 wa0 = *reinterpret_cast<const ulonglong2*>(wp);
                ulonglong2 wb0 = *reinterpret_cast<const ulonglong2*>(wp + 4);
                ulonglong2 wa1 = *reinterpret_cast<const ulonglong2*>(wp + 256);
                ulonglong2 wb1 = *reinterpret_cast<const ulonglong2*>(wp + 260);
#pragma unroll
                for (int b = 0; b < NB; b++) {
                    ulonglong2 hq = *reinterpret_cast<const ulonglong2*>(&sH1[w][b][2 * j2]);
                    a2[b][0] = ffma2(hq.x, wa0.x, a2[b][0]);
                    a2[b][1] = ffma2(hq.x, wa0.y, a2[b][1]);
                    a2[b][2] = ffma2(hq.x, wb0.x, a2[b][2]);
                    a2[b][3] = ffma2(hq.x, wb0.y, a2[b][3]);
                    a2[b][0] = ffma2(hq.y, wa1.x, a2[b][0]);
                    a2[b][1] = ffma2(hq.y, wa1.y, a2[b][1]);
                    a2[b][2] = ffma2(hq.y, wb1.x, a2[b][2]);
                    a2[b][3] = ffma2(hq.y, wb1.y, a2[b][3]);
                }
            }

            // tanh + einsum with dX
            float kk[NB];
#pragma unroll
            for (int b = 0; b < NB; b++) {
                ulonglong2 dx0 = *reinterpret_cast<const ulonglong2*>(&sDX[w][slot][b][0]);
                ulonglong2 dx1 = *reinterpret_cast<const ulonglong2*>(&sDX[w][slot][b][4]);
                ull e = 0ull;
                float p0, p1;
                upk2(a2[b][0], p0, p1); e = ffma2(pk2(tanh_(p0), tanh_(p1)), dx0.x, e);
                upk2(a2[b][1], p0, p1); e = ffma2(pk2(tanh_(p0), tanh_(p1)), dx0.y, e);
                upk2(a2[b][2], p0, p1); e = ffma2(pk2(tanh_(p0), tanh_(p1)), dx1.x, e);
                upk2(a2[b][3], p0, p1); e = ffma2(pk2(tanh_(p0), tanh_(p1)), dx1.y, e);
                float e0, e1; upk2(e, e0, e1);
                kk[b] = e0 + e1;
            }

            // RK4 bookkeeping: weights 1,2,2,1 ; next-stage offsets 0.25,0.25,0.5
            const float wk = (s == 1 || s == 2) ? 2.f : 1.f;
            const float an = (s < 2) ? 0.25f : 0.5f;
#pragma unroll
            for (int b = 0; b < NB; b++) {
                ksum[b] = fmaf(wk, kk[b], ksum[b]);
                zs[b]   = fmaf(an, kk[b], z[b]);
            }
        }
#pragma unroll
        for (int b = 0; b < NB; b++) z[b] = fmaf(ksum[b], (1.f / 12.f), z[b]);  // h/6 = 1/12
    }

    // output head: out = softplus(z @ Wo1^T + bo1) @ Wo2^T + bo2
    __syncwarp();
#pragma unroll
    for (int b = 0; b < NB; b++) sZ[w][b][lane] = z[b];
    __syncwarp();
    float* so = reinterpret_cast<float*>(&sH1[w][0][0]);  // reuse as [NB][16] scratch
    if (lane < 16) {
#pragma unroll
        for (int b = 0; b < NB; b++) {
            float acc = __ldg(bo1 + lane);
#pragma unroll
            for (int hh = 0; hh < 32; hh++)
                acc = fmaf(sZ[w][b][hh], __ldg(Wo1 + lane * 32 + hh), acc);
            so[b * 16 + lane] = sp_(acc);
        }
    }
    __syncwarp();
    if (lane < 24) {
        int b = lane / 3;
        int jo = lane - 3 * b;
        float acc = __ldg(bo2 + jo);
#pragma unroll
        for (int i2 = 0; i2 < 16; i2++)
            acc = fmaf(so[b * 16 + i2], __ldg(Wo2 + jo * 16 + i2), acc);
        out[(size_t)(bbase + b) * 3 + jo] = acc;
    }
}

extern "C" void kernel_launch(void* const* d_in, const int* in_sizes, int n_in,
                              void* d_out, int out_size) {
    const float* X     = (const float*)d_in[0];
    const float* Winit = (const float*)d_in[1];
    const float* binit = (const float*)d_in[2];
    const float* Wf1   = (const float*)d_in[3];
    const float* bf1   = (const float*)d_in[4];
    const float* Wf2   = (const float*)d_in[5];
    const float* bf2   = (const float*)d_in[6];
    const float* Wo1   = (const float*)d_in[7];
    const float* bo1   = (const float*)d_in[8];
    const float* Wo2   = (const float*)d_in[9];
    const float* bo2   = (const float*)d_in[10];
    float* out = (float*)d_out;

    const int B = 4096;
    const int blocks = B / (NWARP * NB);  // 256
    cde_kernel<<<blocks, NWARP * 32>>>(X, Winit, binit, Wf1, bf1, Wf2, bf2,
                                       Wo1, bo1, Wo2, bo2, out);
}

// round 3
// speedup vs baseline: 1.2158x; 1.2158x over previous
#include <cuda_runtime.h>

#define NWARP 4      // warps per block
#define NB 4         // batch elements per warp
#define L 64
#define C 7
#define H 32
#define NSTEPS 126   // (L-1)*K, K=2, h = 0.5

typedef unsigned long long ull;

// ---- packed dual-fp32 FMA (sm_10x) ----
__device__ __forceinline__ ull ffma2(ull a, ull b, ull c) {
    ull d;
    asm("fma.rn.f32x2 %0, %1, %2, %3;" : "=l"(d) : "l"(a), "l"(b), "l"(c));
    return d;
}
__device__ __forceinline__ ull pk2(float x, float y) {
    ull r;
    asm("mov.b64 %0, {%1, %2};" : "=l"(r) : "f"(x), "f"(y));
    return r;
}
__device__ __forceinline__ void upk2(ull v, float &x, float &y) {
    asm("mov.b64 {%0, %1}, %2;" : "=f"(x), "=f"(y) : "l"(v));
}

// stable softplus: max(x,0) + log(1+exp(-|x|)); abs err ~1e-7
__device__ __forceinline__ float sp_(float x) {
    return fmaxf(x, 0.f) + __logf(1.f + __expf(-fabsf(x)));
}
// HW tanh approx (single MUFU), ~1e-5 abs err; tolerance budget 1e-3
__device__ __forceinline__ float tanh_(float x) {
    float y;
    asm("tanh.approx.f32 %0, %1;" : "=f"(y) : "f"(x));
    return y;
}

// cubic Hermite derivative: dX = m0 + (diff-m0)*f*(4-3f)
__device__ __forceinline__ float spline_eval(const float* __restrict__ xrow, float t) {
    int idx = (int)t;
    idx = min(idx, L - 2);
    float f = t - (float)idx;
    const float* p = xrow + idx * C;
    float x0 = __ldg(p);
    float x1 = __ldg(p + C);
    float diff = x1 - x0;
    float m0 = diff;
    if (idx > 0) m0 = x0 - __ldg(p - C);
    return fmaf((diff - m0) * f, fmaf(-3.f, f, 4.f), m0);
}

__global__ __launch_bounds__(NWARP * 32)
void cde_kernel(const float* __restrict__ X,      // (4096,64,7)
                const float* __restrict__ Winit,  // (32,7)
                const float* __restrict__ binit,  // (32)
                const float* __restrict__ Wf1,    // (32,32)
                const float* __restrict__ bf1,    // (32)
                const float* __restrict__ Wf2,    // (224,32)
                const float* __restrict__ bf2,    // (224)
                const float* __restrict__ Wo1,    // (16,32)
                const float* __restrict__ bo1,    // (16)
                const float* __restrict__ Wo2,    // (3,16)
                const float* __restrict__ bo2,    // (3)
                float* __restrict__ out)          // (4096,3)
{
    // Wf2 transposed + padded: sW2[j][h*8 + c] = Wf2[h*7+c][j], c==7 -> 0
    __shared__ __align__(16) float sW2[32][256];             // 32 KB (shared by all warps)
    __shared__ __align__(16) float sZ[NWARP][NB][32];        // 2 KB
    __shared__ __align__(16) ull   sH1[NWARP][NB][32];       // 4 KB  (duplicated pairs)
    __shared__ __align__(16) float sDX[NWARP][3][NB][8];     // 1.5 KB

    const int tid = threadIdx.x;
    const int w = tid >> 5;
    const int lane = tid & 31;

    for (int i = tid; i < 32 * 256; i += NWARP * 32) {
        int j = i >> 8, hc = i & 255, h = hc >> 3, c = hc & 7;
        sW2[j][hc] = (c < C) ? Wf2[(h * C + c) * 32 + j] : 0.f;
    }
    __syncthreads();

    const int bbase = (blockIdx.x * NWARP + w) * NB;

    // per-lane constant registers (lane = h)
    ull rw1[16];
    {
        const float2* p = reinterpret_cast<const float2*>(Wf1 + lane * 32);
#pragma unroll
        for (int k = 0; k < 16; k++) { float2 v = __ldg(p + k); rw1[k] = pk2(v.x, v.y); }
    }
    const float rbf1 = __ldg(bf1 + lane);
    ull rbf2[4];
#pragma unroll
    for (int cp = 0; cp < 4; cp++) {
        int c0 = 2 * cp, c1 = 2 * cp + 1;
        float a = __ldg(bf2 + lane * C + c0);
        float b = (c1 < C) ? __ldg(bf2 + lane * C + c1) : 0.f;
        rbf2[cp] = pk2(a, b);
    }

    // dX lane mapping: 8 lanes per batch; lane -> (batch db, channel dc)
    const int db = lane >> 3;        // 0..3
    const int dc = lane & 7;         // 0..7 (7 = pad)
    const float* xrow = X + (size_t)(bbase + db) * (L * C) + ((dc < C) ? dc : 0);

    // z0 = x[:,0] @ Winit^T + binit
    float z[NB];
#pragma unroll
    for (int b = 0; b < NB; b++) {
        float acc = __ldg(binit + lane);
        const float* xp = X + (size_t)(bbase + b) * (L * C);
#pragma unroll
        for (int c = 0; c < C; c++) acc = fmaf(__ldg(xp + c), __ldg(Winit + lane * C + c), acc);
        z[b] = acc;
    }

    // initial dX(t=0) -> slot 0  (idx=0, f=0 -> dX = x[1]-x[0])
    {
        float v = 0.f;
        if (dc < C) v = __ldg(xrow + C) - __ldg(xrow);
        sDX[w][0][db][dc] = v;
    }
    __syncwarp();

    float t0 = 0.f;
#pragma unroll 1
    for (int i = 0; i < NSTEPS; i++, t0 += 0.5f) {
        // dX at t0+0.25 -> slot 2 ; dX at t0+0.5 -> slot (i+1)&1 (next step's A)
        {
            float vb = 0.f, vc = 0.f;
            if (dc < C) {
                vb = spline_eval(xrow, t0 + 0.25f);
                vc = spline_eval(xrow, t0 + 0.5f);
            }
            __syncwarp();
            sDX[w][2][db][dc] = vb;
            sDX[w][(i + 1) & 1][db][dc] = vc;
            __syncwarp();
        }
        const int slotA = i & 1;
        const int slotC = (i + 1) & 1;

        float ksum[NB], zs[NB];
#pragma unroll
        for (int b = 0; b < NB; b++) { zs[b] = z[b]; ksum[b] = 0.f; }

#pragma unroll 1
        for (int s = 0; s < 4; s++) {
            const int slot = (s == 0) ? slotA : ((s == 3) ? slotC : 2);

            // ---- vf(zs) ----
            __syncwarp();
#pragma unroll
            for (int b = 0; b < NB; b++) sZ[w][b][lane] = zs[b];
            __syncwarp();

            // mm1: h1_pre[lane] = sum_j zs[j]*Wf1[lane][j]   (128-bit z broadcasts)
            ull a1[NB];
#pragma unroll
            for (int b = 0; b < NB; b++) a1[b] = 0ull;
#pragma unroll
            for (int k4 = 0; k4 < 8; k4++) {
#pragma unroll
                for (int b = 0; b < NB; b++) {
                    ulonglong2 zq = *reinterpret_cast<const ulonglong2*>(&sZ[w][b][4 * k4]);
                    a1[b] = ffma2(zq.x, rw1[2 * k4], a1[b]);
                    a1[b] = ffma2(zq.y, rw1[2 * k4 + 1], a1[b]);
                }
            }
            float h1[NB];
#pragma unroll
            for (int b = 0; b < NB; b++) {
                float u, v; upk2(a1[b], u, v);
                h1[b] = sp_(u + v + rbf1);
            }
            __syncwarp();
#pragma unroll
            for (int b = 0; b < NB; b++) sH1[w][b][lane] = pk2(h1[b], h1[b]);
            __syncwarp();

            // mm2: g_pre[lane*7+c] = sum_j h1[j]*Wf2[lane*7+c][j]  (c packed, j x2)
            ull a2[NB][4];
#pragma unroll
            for (int b = 0; b < NB; b++)
#pragma unroll
                for (int cp = 0; cp < 4; cp++) a2[b][cp] = rbf2[cp];

            const float* wrow = &sW2[0][lane * 8];
#pragma unroll 4
            for (int j2 = 0; j2 < 16; j2++) {
                const float* wp = wrow + (2 * j2) * 256;
                ulonglong2 wa0 = *reinterpret_cast<const ulonglong2*>(wp);
                ulonglong2 wb0 = *reinterpret_cast<const ulonglong2*>(wp + 4);
                ulonglong2 wa1 = *reinterpret_cast<const ulonglong2*>(wp + 256);
                ulonglong2 wb1 = *reinterpret_cast<const ulonglong2*>(wp + 260);
#pragma unroll
                for (int b = 0; b < NB; b++) {
                    ulonglong2 hq = *reinterpret_cast<const ulonglong2*>(&sH1[w][b][2 * j2]);
                    a2[b][0] = ffma2(hq.x, wa0.x, a2[b][0]);
                    a2[b][1] = ffma2(hq.x, wa0.y, a2[b][1]);
                    a2[b][2] = ffma2(hq.x, wb0.x, a2[b][2]);
                    a2[b][3] = ffma2(hq.x, wb0.y, a2[b][3]);
                    a2[b][0] = ffma2(hq.y, wa1.x, a2[b][0]);
                    a2[b][1] = ffma2(hq.y, wa1.y, a2[b][1]);
                    a2[b][2] = ffma2(hq.y, wb1.x, a2[b][2]);
                    a2[b][3] = ffma2(hq.y, wb1.y, a2[b][3]);
                }
            }

            // tanh + einsum with dX
            float kk[NB];
#pragma unroll
            for (int b = 0; b < NB; b++) {
                ulonglong2 dx0 = *reinterpret_cast<const ulonglong2*>(&sDX[w][slot][b][0]);
                ulonglong2 dx1 = *reinterpret_cast<const ulonglong2*>(&sDX[w][slot][b][4]);
                ull e = 0ull;
                float p0, p1;
                upk2(a2[b][0], p0, p1); e = ffma2(pk2(tanh_(p0), tanh_(p1)), dx0.x, e);
                upk2(a2[b][1], p0, p1); e = ffma2(pk2(tanh_(p0), tanh_(p1)), dx0.y, e);
                upk2(a2[b][2], p0, p1); e = ffma2(pk2(tanh_(p0), tanh_(p1)), dx1.x, e);
                upk2(a2[b][3], p0, p1); e = ffma2(pk2(tanh_(p0), tanh_(p1)), dx1.y, e);
                float e0, e1; upk2(e, e0, e1);
                kk[b] = e0 + e1;
            }

            // RK4 bookkeeping: weights 1,2,2,1 ; next-stage offsets 0.25,0.25,0.5
            const float wk = (s == 1 || s == 2) ? 2.f : 1.f;
            const float an = (s < 2) ? 0.25f : 0.5f;
#pragma unroll
            for (int b = 0; b < NB; b++) {
                ksum[b] = fmaf(wk, kk[b], ksum[b]);
                zs[b]   = fmaf(an, kk[b], z[b]);
            }
        }
#pragma unroll
        for (int b = 0; b < NB; b++) z[b] = fmaf(ksum[b], (1.f / 12.f), z[b]);  // h/6 = 1/12
    }

    // output head: out = softplus(z @ Wo1^T + bo1) @ Wo2^T + bo2
    __syncwarp();
#pragma unroll
    for (int b = 0; b < NB; b++) sZ[w][b][lane] = z[b];
    __syncwarp();
    float* so = reinterpret_cast<float*>(&sH1[w][0][0]);  // reuse as [NB][16] scratch
    if (lane < 16) {
#pragma unroll
        for (int b = 0; b < NB; b++) {
            float acc = __ldg(bo1 + lane);
#pragma unroll
            for (int hh = 0; hh < 32; hh++)
                acc = fmaf(sZ[w][b][hh], __ldg(Wo1 + lane * 32 + hh), acc);
            so[b * 16 + lane] = sp_(acc);
        }
    }
    __syncwarp();
    if (lane < 12) {
        int b = lane / 3;
        int jo = lane - 3 * b;
        float acc = __ldg(bo2 + jo);
#pragma unroll
        for (int i2 = 0; i2 < 16; i2++)
            acc = fmaf(so[b * 16 + i2], __ldg(Wo2 + jo * 16 + i2), acc);
        out[(size_t)(bbase + b) * 3 + jo] = acc;
    }
}

extern "C" void kernel_launch(void* const* d_in, const int* in_sizes, int n_in,
                              void* d_out, int out_size) {
    const float* X     = (const float*)d_in[0];
    const float* Winit = (const float*)d_in[1];
    const float* binit = (const float*)d_in[2];
    const float* Wf1   = (const float*)d_in[3];
    const float* bf1   = (const float*)d_in[4];
    const float* Wf2   = (const float*)d_in[5];
    const float* bf2   = (const float*)d_in[6];
    const float* Wo1   = (const float*)d_in[7];
    const float* bo1   = (const float*)d_in[8];
    const float* Wo2   = (const float*)d_in[9];
    const float* bo2   = (const float*)d_in[10];
    float* out = (float*)d_out;

    const int B = 4096;
    const int blocks = B / (NWARP * NB);  // 256
    cde_kernel<<<blocks, NWARP * 32>>>(X, Winit, binit, Wf1, bf1, Wf2, bf2,
                                       Wo1, bo1, Wo2, bo2, out);
}

// round 4
// speedup vs baseline: 1.5232x; 1.2529x over previous
#include <cuda_runtime.h>

#define NWARP 7      // warps per block (148 blocks -> one CTA per SM, single wave)
#define NB 4         // batch elements per warp
#define NBLK 148
#define L 64
#define C 7
#define H 32
#define NSTEPS 126   // (L-1)*K, K=2, h = 0.5

typedef unsigned long long ull;

// ---- packed dual-fp32 FMA (sm_10x) ----
__device__ __forceinline__ ull ffma2(ull a, ull b, ull c) {
    ull d;
    asm("fma.rn.f32x2 %0, %1, %2, %3;" : "=l"(d) : "l"(a), "l"(b), "l"(c));
    return d;
}
__device__ __forceinline__ ull pk2(float x, float y) {
    ull r;
    asm("mov.b64 %0, {%1, %2};" : "=l"(r) : "f"(x), "f"(y));
    return r;
}
__device__ __forceinline__ void upk2(ull v, float &x, float &y) {
    asm("mov.b64 {%0, %1}, %2;" : "=f"(x), "=f"(y) : "l"(v));
}

// stable softplus: max(x,0) + log(1+exp(-|x|)); abs err ~1e-7
__device__ __forceinline__ float sp_(float x) {
    return fmaxf(x, 0.f) + __logf(1.f + __expf(-fabsf(x)));
}
// HW tanh approx (single MUFU), ~1e-5 abs err; tolerance budget 1e-3
__device__ __forceinline__ float tanh_(float x) {
    float y;
    asm("tanh.approx.f32 %0, %1;" : "=f"(y) : "f"(x));
    return y;
}

// cubic Hermite derivative: dX = m0 + (diff-m0)*f*(4-3f)
__device__ __forceinline__ float spline_eval(const float* __restrict__ xrow, float t) {
    int idx = (int)t;
    idx = min(idx, L - 2);
    float f = t - (float)idx;
    const float* p = xrow + idx * C;
    float x0 = __ldg(p);
    float x1 = __ldg(p + C);
    float diff = x1 - x0;
    float m0 = diff;
    if (idx > 0) m0 = x0 - __ldg(p - C);
    return fmaf((diff - m0) * f, fmaf(-3.f, f, 4.f), m0);
}

__global__ __launch_bounds__(NWARP * 32)
void cde_kernel(const float* __restrict__ X,      // (4096,64,7)
                const float* __restrict__ Winit,  // (32,7)
                const float* __restrict__ binit,  // (32)
                const float* __restrict__ Wf1,    // (32,32)
                const float* __restrict__ bf1,    // (32)
                const float* __restrict__ Wf2,    // (224,32)
                const float* __restrict__ bf2,    // (224)
                const float* __restrict__ Wo1,    // (16,32)
                const float* __restrict__ bo1,    // (16)
                const float* __restrict__ Wo2,    // (3,16)
                const float* __restrict__ bo2,    // (3)
                float* __restrict__ out)          // (4096,3)
{
    // Wf2 transposed + padded: sW2[j][h*8 + c] = Wf2[h*7+c][j], c==7 -> 0
    __shared__ __align__(16) float sW2[32][256];             // 32 KB (shared by all warps)
    __shared__ __align__(16) float sZ[NWARP][NB][32];        // 3.5 KB
    __shared__ __align__(16) ull   sH1[NWARP][NB][32];       // 7 KB  (duplicated pairs)
    __shared__ __align__(16) float sDX[NWARP][3][NB][8];     // 2.6 KB

    const int tid = threadIdx.x;
    const int w = tid >> 5;
    const int lane = tid & 31;

    for (int i = tid; i < 32 * 256; i += NWARP * 32) {
        int j = i >> 8, hc = i & 255, h = hc >> 3, c = hc & 7;
        sW2[j][hc] = (c < C) ? Wf2[(h * C + c) * 32 + j] : 0.f;
    }
    __syncthreads();

    const int gw = blockIdx.x * NWARP + w;     // global warp id
    const int bbase = gw * NB;
    if (bbase >= 4096) return;                 // surplus warps exit (post-barrier)

    // per-lane constant registers (lane = h)
    ull rw1[16];
    {
        const float2* p = reinterpret_cast<const float2*>(Wf1 + lane * 32);
#pragma unroll
        for (int k = 0; k < 16; k++) { float2 v = __ldg(p + k); rw1[k] = pk2(v.x, v.y); }
    }
    const float rbf1 = __ldg(bf1 + lane);
    ull rbf2[4];
#pragma unroll
    for (int cp = 0; cp < 4; cp++) {
        int c0 = 2 * cp, c1 = 2 * cp + 1;
        float a = __ldg(bf2 + lane * C + c0);
        float b = (c1 < C) ? __ldg(bf2 + lane * C + c1) : 0.f;
        rbf2[cp] = pk2(a, b);
    }

    // dX lane mapping: 8 lanes per batch; lane -> (batch db, channel dc)
    const int db = lane >> 3;        // 0..3
    const int dc = lane & 7;         // 0..7 (7 = pad)
    const float* xrow = X + (size_t)(bbase + db) * (L * C) + ((dc < C) ? dc : 0);

    // z0 = x[:,0] @ Winit^T + binit
    float z[NB];
#pragma unroll
    for (int b = 0; b < NB; b++) {
        float acc = __ldg(binit + lane);
        const float* xp = X + (size_t)(bbase + b) * (L * C);
#pragma unroll
        for (int c = 0; c < C; c++) acc = fmaf(__ldg(xp + c), __ldg(Winit + lane * C + c), acc);
        z[b] = acc;
    }

    // initial dX(t=0) -> slot 0  (idx=0, f=0 -> dX = x[1]-x[0])
    {
        float v = 0.f;
        if (dc < C) v = __ldg(xrow + C) - __ldg(xrow);
        sDX[w][0][db][dc] = v;
    }
    __syncwarp();

    float t0 = 0.f;
#pragma unroll 1
    for (int i = 0; i < NSTEPS; i++, t0 += 0.5f) {
        // dX at t0+0.25 -> slot 2 ; dX at t0+0.5 -> slot (i+1)&1 (next step's A)
        {
            float vb = 0.f, vc = 0.f;
            if (dc < C) {
                vb = spline_eval(xrow, t0 + 0.25f);
                vc = spline_eval(xrow, t0 + 0.5f);
            }
            __syncwarp();
            sDX[w][2][db][dc] = vb;
            sDX[w][(i + 1) & 1][db][dc] = vc;
            __syncwarp();
        }
        const int slotA = i & 1;
        const int slotC = (i + 1) & 1;

        float ksum[NB], zs[NB];
#pragma unroll
        for (int b = 0; b < NB; b++) { zs[b] = z[b]; ksum[b] = 0.f; }

#pragma unroll 1
        for (int s = 0; s < 4; s++) {
            const int slot = (s == 0) ? slotA : ((s == 3) ? slotC : 2);

            // ---- vf(zs) ----
            __syncwarp();
#pragma unroll
            for (int b = 0; b < NB; b++) sZ[w][b][lane] = zs[b];
            __syncwarp();

            // mm1: h1_pre[lane] = sum_j zs[j]*Wf1[lane][j]   (128-bit z broadcasts)
            ull a1[NB];
#pragma unroll
            for (int b = 0; b < NB; b++) a1[b] = 0ull;
#pragma unroll
            for (int k4 = 0; k4 < 8; k4++) {
#pragma unroll
                for (int b = 0; b < NB; b++) {
                    ulonglong2 zq = *reinterpret_cast<const ulonglong2*>(&sZ[w][b][4 * k4]);
                    a1[b] = ffma2(zq.x, rw1[2 * k4], a1[b]);
                    a1[b] = ffma2(zq.y, rw1[2 * k4 + 1], a1[b]);
                }
            }
            float h1[NB];
#pragma unroll
            for (int b = 0; b < NB; b++) {
                float u, v; upk2(a1[b], u, v);
                h1[b] = sp_(u + v + rbf1);
            }
            __syncwarp();
#pragma unroll
            for (int b = 0; b < NB; b++) sH1[w][b][lane] = pk2(h1[b], h1[b]);
            __syncwarp();

            // mm2: g_pre[lane*7+c] = sum_j h1[j]*Wf2[lane*7+c][j]
            // FULL unroll -> ptxas front-batches the sW2 loads (MLP)
            ull a2[NB][4];
#pragma unroll
            for (int b = 0; b < NB; b++)
#pragma unroll
                for (int cp = 0; cp < 4; cp++) a2[b][cp] = rbf2[cp];

            const float* wrow = &sW2[0][lane * 8];
#pragma unroll
            for (int j2 = 0; j2 < 16; j2++) {
                const float* wp = wrow + (2 * j2) * 256;
                ulonglong2 wa0 = *reinterpret_cast<const ulonglong2*>(wp);
                ulonglong2 wb0 = *reinterpret_cast<const ulonglong2*>(wp + 4);
                ulonglong2 wa1 = *reinterpret_cast<const ulonglong2*>(wp + 256);
                ulonglong2 wb1 = *reinterpret_cast<const ulonglong2*>(wp + 260);
#pragma unroll
                for (int b = 0; b < NB; b++) {
                    ulonglong2 hq = *reinterpret_cast<const ulonglong2*>(&sH1[w][b][2 * j2]);
                    a2[b][0] = ffma2(hq.x, wa0.x, a2[b][0]);
                    a2[b][1] = ffma2(hq.x, wa0.y, a2[b][1]);
                    a2[b][2] = ffma2(hq.x, wb0.x, a2[b][2]);
                    a2[b][3] = ffma2(hq.x, wb0.y, a2[b][3]);
                    a2[b][0] = ffma2(hq.y, wa1.x, a2[b][0]);
                    a2[b][1] = ffma2(hq.y, wa1.y, a2[b][1]);
                    a2[b][2] = ffma2(hq.y, wb1.x, a2[b][2]);
                    a2[b][3] = ffma2(hq.y, wb1.y, a2[b][3]);
                }
            }

            // tanh + einsum with dX
            float kk[NB];
#pragma unroll
            for (int b = 0; b < NB; b++) {
                ulonglong2 dx0 = *reinterpret_cast<const ulonglong2*>(&sDX[w][slot][b][0]);
                ulonglong2 dx1 = *reinterpret_cast<const ulonglong2*>(&sDX[w][slot][b][4]);
                ull e = 0ull;
                float p0, p1;
                upk2(a2[b][0], p0, p1); e = ffma2(pk2(tanh_(p0), tanh_(p1)), dx0.x, e);
                upk2(a2[b][1], p0, p1); e = ffma2(pk2(tanh_(p0), tanh_(p1)), dx0.y, e);
                upk2(a2[b][2], p0, p1); e = ffma2(pk2(tanh_(p0), tanh_(p1)), dx1.x, e);
                upk2(a2[b][3], p0, p1); e = ffma2(pk2(tanh_(p0), tanh_(p1)), dx1.y, e);
                float e0, e1; upk2(e, e0, e1);
                kk[b] = e0 + e1;
            }

            // RK4 bookkeeping: weights 1,2,2,1 ; next-stage offsets 0.25,0.25,0.5
            const float wk = (s == 1 || s == 2) ? 2.f : 1.f;
            const float an = (s < 2) ? 0.25f : 0.5f;
#pragma unroll
            for (int b = 0; b < NB; b++) {
                ksum[b] = fmaf(wk, kk[b], ksum[b]);
                zs[b]   = fmaf(an, kk[b], z[b]);
            }
        }
#pragma unroll
        for (int b = 0; b < NB; b++) z[b] = fmaf(ksum[b], (1.f / 12.f), z[b]);  // h/6 = 1/12
    }

    // output head: out = softplus(z @ Wo1^T + bo1) @ Wo2^T + bo2
    __syncwarp();
#pragma unroll
    for (int b = 0; b < NB; b++) sZ[w][b][lane] = z[b];
    __syncwarp();
    float* so = reinterpret_cast<float*>(&sH1[w][0][0]);  // reuse as [NB][16] scratch
    if (lane < 16) {
#pragma unroll
        for (int b = 0; b < NB; b++) {
            float acc = __ldg(bo1 + lane);
#pragma unroll
            for (int hh = 0; hh < 32; hh++)
                acc = fmaf(sZ[w][b][hh], __ldg(Wo1 + lane * 32 + hh), acc);
            so[b * 16 + lane] = sp_(acc);
        }
    }
    __syncwarp();
    if (lane < 12) {
        int b = lane / 3;
        int jo = lane - 3 * b;
        float acc = __ldg(bo2 + jo);
#pragma unroll
        for (int i2 = 0; i2 < 16; i2++)
            acc = fmaf(so[b * 16 + i2], __ldg(Wo2 + jo * 16 + i2), acc);
        out[(size_t)(bbase + b) * 3 + jo] = acc;
    }
}

extern "C" void kernel_launch(void* const* d_in, const int* in_sizes, int n_in,
                              void* d_out, int out_size) {
    const float* X     = (const float*)d_in[0];
    const float* Winit = (const float*)d_in[1];
    const float* binit = (const float*)d_in[2];
    const float* Wf1   = (const float*)d_in[3];
    const float* bf1   = (const float*)d_in[4];
    const float* Wf2   = (const float*)d_in[5];
    const float* bf2   = (const float*)d_in[6];
    const float* Wo1   = (const float*)d_in[7];
    const float* bo1   = (const float*)d_in[8];
    const float* Wo2   = (const float*)d_in[9];
    const float* bo2   = (const float*)d_in[10];
    float* out = (float*)d_out;

    cde_kernel<<<NBLK, NWARP * 32>>>(X, Winit, binit, Wf1, bf1, Wf2, bf2,
                                     Wo1, bo1, Wo2, bo2, out);
}

// round 5
// speedup vs baseline: 1.6858x; 1.1067x over previous
#include <cuda_runtime.h>

#define L 64
#define C 7
#define NSTEPS 126   // (L-1)*K, K=2, h=0.5

typedef unsigned long long ull;

// ---- packed dual-fp32 FMA (sm_10x) ----
__device__ __forceinline__ ull ffma2(ull a, ull b, ull c) {
    ull d;
    asm("fma.rn.f32x2 %0, %1, %2, %3;" : "=l"(d) : "l"(a), "l"(b), "l"(c));
    return d;
}
__device__ __forceinline__ ull pk2(float x, float y) {
    ull r;
    asm("mov.b64 %0, {%1, %2};" : "=l"(r) : "f"(x), "f"(y));
    return r;
}
__device__ __forceinline__ void upk2(ull v, float &x, float &y) {
    asm("mov.b64 {%0, %1}, %2;" : "=f"(x), "=f"(y) : "l"(v));
}

// stable softplus
__device__ __forceinline__ float sp_(float x) {
    return fmaxf(x, 0.f) + __logf(1.f + __expf(-fabsf(x)));
}
// HW tanh approx (single MUFU), ~1e-5 abs err
__device__ __forceinline__ float tanh_(float x) {
    float y;
    asm("tanh.approx.f32 %0, %1;" : "=f"(y) : "f"(x));
    return y;
}

// cubic Hermite derivative: dX = m0 + (diff-m0)*f*(4-3f)
__device__ __forceinline__ float spline_eval(const float* __restrict__ xrow, float t) {
    int idx = (int)t;
    idx = min(idx, L - 2);
    float f = t - (float)idx;
    const float* p = xrow + idx * C;
    float x0 = __ldg(p);
    float x1 = __ldg(p + C);
    float diff = x1 - x0;
    float m0 = diff;
    if (idx > 0) m0 = x0 - __ldg(p - C);
    return fmaf((diff - m0) * f, fmaf(-3.f, f, 4.f), m0);
}

__global__ __launch_bounds__(256, 1)
void cde_kernel(const float* __restrict__ X,      // (4096,64,7)
                const float* __restrict__ Winit,  // (32,7)
                const float* __restrict__ binit,  // (32)
                const float* __restrict__ Wf1,    // (32,32)
                const float* __restrict__ bf1,    // (32)
                const float* __restrict__ Wf2,    // (224,32)
                const float* __restrict__ bf2,    // (224)
                const float* __restrict__ Wo1,    // (16,32)
                const float* __restrict__ bo1,    // (16)
                const float* __restrict__ Wo2,    // (3,16)
                const float* __restrict__ bo2,    // (3)
                float* __restrict__ out)          // (4096,3)
{
    // 8 warps = 4 pairs; pair p serves 8 batches; warp A: c0-3, warp B: c4-7(pad)
    __shared__ __align__(16) float sZ[4][8][32];      // 4 KB  (zs, lane=h)
    __shared__ __align__(16) float sH1[4][8][32];     // 4 KB  (plain h1)
    __shared__ __align__(16) float sDX[4][3][8][8];   // 3 KB
    __shared__ __align__(16) float sPart[8][8][32];   // 8 KB  (einsum partials per warp)

    const int tid  = threadIdx.x;
    const int w    = tid >> 5;
    const int lane = tid & 31;          // = h
    const int pair = w >> 1;
    const int isB  = w & 1;
    const int partner = w ^ 1;
    const int pairbase = (blockIdx.x * 4 + pair) * 8;
    const int ownbase  = pairbase + isB * 4;   // first of own 4 batches

    // ---- Wf2 own c-half, j-pair packed, in REGISTERS (128 regs) ----
    ull wreg[4][16];
    float b2[4];
#pragma unroll
    for (int cp = 0; cp < 4; cp++) {
        int cg = isB * 4 + cp;
        if (cg < C) {
            const float2* wp = reinterpret_cast<const float2*>(Wf2 + (lane * C + cg) * 32);
#pragma unroll
            for (int jp = 0; jp < 16; jp++) { float2 v = __ldg(wp + jp); wreg[cp][jp] = pk2(v.x, v.y); }
            b2[cp] = __ldg(bf2 + lane * C + cg);
        } else {
#pragma unroll
            for (int jp = 0; jp < 16; jp++) wreg[cp][jp] = 0ull;
            b2[cp] = 0.f;
        }
    }
    // Wf1 row, j-pair packed
    ull rw1[16];
    {
        const float2* p1 = reinterpret_cast<const float2*>(Wf1 + lane * 32);
#pragma unroll
        for (int jp = 0; jp < 16; jp++) { float2 v = __ldg(p1 + jp); rw1[jp] = pk2(v.x, v.y); }
    }
    const float rbf1 = __ldg(bf1 + lane);

    // dX mapping over own 4 batches: lane -> (db, dc)
    const int db = lane >> 3;
    const int dc = lane & 7;
    const float* xrow = X + (size_t)(ownbase + db) * (L * C) + ((dc < C) ? dc : 0);

    // z0 for own 4 batches
    float z[4];
#pragma unroll
    for (int k = 0; k < 4; k++) {
        float acc = __ldg(binit + lane);
        const float* xp = X + (size_t)(ownbase + k) * (L * C);
#pragma unroll
        for (int c = 0; c < C; c++) acc = fmaf(__ldg(xp + c), __ldg(Winit + lane * C + c), acc);
        z[k] = acc;
    }

    // initial dX(t=0) -> slot 0
    {
        float v = 0.f;
        if (dc < C) v = __ldg(xrow + C) - __ldg(xrow);
        sDX[pair][0][isB * 4 + db][dc] = v;
    }

    float t0 = 0.f;
#pragma unroll 1
    for (int i = 0; i < NSTEPS; i++, t0 += 0.5f) {
        // spline: t0+0.25 -> slot 2 ; t0+0.5 -> slot (i+1)&1
        {
            float vb = 0.f, vc = 0.f;
            if (dc < C) {
                vb = spline_eval(xrow, t0 + 0.25f);
                vc = spline_eval(xrow, t0 + 0.5f);
            }
            sDX[pair][2][isB * 4 + db][dc] = vb;
            sDX[pair][(i + 1) & 1][isB * 4 + db][dc] = vc;
        }
        const int slotA = i & 1, slotC = (i + 1) & 1;

        float zs[4], ksum[4];
#pragma unroll
        for (int k = 0; k < 4; k++) { zs[k] = z[k]; ksum[k] = 0.f; }

#pragma unroll 1
        for (int s = 0; s < 4; s++) {
            const int slot = (s == 0) ? slotA : ((s == 3) ? slotC : 2);

            // own zs -> sZ ; mm1 (own 4 b) ; h1 -> sH1
            __syncwarp();
#pragma unroll
            for (int k = 0; k < 4; k++) sZ[pair][isB * 4 + k][lane] = zs[k];
            __syncwarp();
#pragma unroll 1
            for (int k = 0; k < 4; k++) {
                const ulonglong2* zp = reinterpret_cast<const ulonglong2*>(&sZ[pair][isB * 4 + k][0]);
                ull a1 = 0ull;
#pragma unroll
                for (int q = 0; q < 8; q++) {
                    ulonglong2 zq = zp[q];
                    a1 = ffma2(zq.x, rw1[2 * q], a1);
                    a1 = ffma2(zq.y, rw1[2 * q + 1], a1);
                }
                float u, v; upk2(a1, u, v);
                sH1[pair][isB * 4 + k][lane] = sp_(u + v + rbf1);
            }
            asm volatile("bar.sync %0, 64;" :: "r"(pair + 1) : "memory");

            // mm2 for all 8 batches of the pair (own c-half, weights in regs)
#pragma unroll 1
            for (int bs = 0; bs < 8; bs++) {
                ull h1p[16];
                const ulonglong2* hp = reinterpret_cast<const ulonglong2*>(&sH1[pair][bs][0]);
#pragma unroll
                for (int q = 0; q < 8; q++) { ulonglong2 v = hp[q]; h1p[2 * q] = v.x; h1p[2 * q + 1] = v.y; }
                ull acc0 = 0ull, acc1 = 0ull, acc2 = 0ull, acc3 = 0ull;
#pragma unroll
                for (int jp = 0; jp < 16; jp++) {
                    acc0 = ffma2(h1p[jp], wreg[0][jp], acc0);
                    acc1 = ffma2(h1p[jp], wreg[1][jp], acc1);
                    acc2 = ffma2(h1p[jp], wreg[2][jp], acc2);
                    acc3 = ffma2(h1p[jp], wreg[3][jp], acc3);
                }
                float u, v, g0, g1, g2, g3;
                upk2(acc0, u, v); g0 = tanh_(u + v + b2[0]);
                upk2(acc1, u, v); g1 = tanh_(u + v + b2[1]);
                upk2(acc2, u, v); g2 = tanh_(u + v + b2[2]);
                upk2(acc3, u, v); g3 = tanh_(u + v + b2[3]);
                ulonglong2 dxp = *reinterpret_cast<const ulonglong2*>(&sDX[pair][slot][bs][isB * 4]);
                ull e = ffma2(pk2(g0, g1), dxp.x, ffma2(pk2(g2, g3), dxp.y, 0ull));
                float e0, e1; upk2(e, e0, e1);
                sPart[w][bs][lane] = e0 + e1;
            }
            asm volatile("bar.sync %0, 64;" :: "r"(pair + 1) : "memory");

            // combine partials for own 4 b; RK4 bookkeeping
            const float wk = (s == 1 || s == 2) ? 2.f : 1.f;
            const float an = (s < 2) ? 0.25f : 0.5f;
#pragma unroll
            for (int k = 0; k < 4; k++) {
                int bs = isB * 4 + k;
                float kk = sPart[w][bs][lane] + sPart[partner][bs][lane];
                ksum[k] = fmaf(wk, kk, ksum[k]);
                zs[k]   = fmaf(an, kk, z[k]);
            }
        }
#pragma unroll
        for (int k = 0; k < 4; k++) z[k] = fmaf(ksum[k], (1.f / 12.f), z[k]);  // h/6
    }

    // make sure partner is done reading our sPart/sH1 before reuse as scratch
    asm volatile("bar.sync %0, 64;" :: "r"(pair + 1) : "memory");

    // output head (own 4 batches): softplus(z @ Wo1^T + bo1) @ Wo2^T + bo2
#pragma unroll
    for (int k = 0; k < 4; k++) sZ[pair][isB * 4 + k][lane] = z[k];
    __syncwarp();
    float* so = &sPart[w][0][0];   // [4][32] scratch, own-warp only
    if (lane < 16) {
#pragma unroll
        for (int k = 0; k < 4; k++) {
            float acc = __ldg(bo1 + lane);
#pragma unroll
            for (int hh = 0; hh < 32; hh++)
                acc = fmaf(sZ[pair][isB * 4 + k][hh], __ldg(Wo1 + lane * 32 + hh), acc);
            so[k * 32 + lane] = sp_(acc);
        }
    }
    __syncwarp();
    if (lane < 12) {
        int k = lane / 3;
        int jo = lane - 3 * k;
        float acc = __ldg(bo2 + jo);
#pragma unroll
        for (int i2 = 0; i2 < 16; i2++)
            acc = fmaf(so[k * 32 + i2], __ldg(Wo2 + jo * 16 + i2), acc);
        out[(size_t)(ownbase + k) * 3 + jo] = acc;
    }
}

extern "C" void kernel_launch(void* const* d_in, const int* in_sizes, int n_in,
                              void* d_out, int out_size) {
    const float* X     = (const float*)d_in[0];
    const float* Winit = (const float*)d_in[1];
    const float* binit = (const float*)d_in[2];
    const float* Wf1   = (const float*)d_in[3];
    const float* bf1   = (const float*)d_in[4];
    const float* Wf2   = (const float*)d_in[5];
    const float* bf2   = (const float*)d_in[6];
    const float* Wo1   = (const float*)d_in[7];
    const float* bo1   = (const float*)d_in[8];
    const float* Wo2   = (const float*)d_in[9];
    const float* bo2   = (const float*)d_in[10];
    float* out = (float*)d_out;

    // 128 blocks x 8 warps: 4 pairs/block x 8 batches = 4096 exactly
    cde_kernel<<<128, 256>>>(X, Winit, binit, Wf1, bf1, Wf2, bf2,
                             Wo1, bo1, Wo2, bo2, out);
}

// round 6
// speedup vs baseline: 1.9328x; 1.1465x over previous
#include <cuda_runtime.h>

#define L 64
#define C 7
#define NSTEPS 126   // (L-1)*K, K=2, h=0.5
#define NBPAIR 7     // batches per warp-pair
#define NPAIRS 586   // ceil(4096/7)
#define NCTA 293     // 2 pairs per CTA

typedef unsigned long long ull;

// ---- packed dual-fp32 FMA (sm_10x) ----
__device__ __forceinline__ ull ffma2(ull a, ull b, ull c) {
    ull d;
    asm("fma.rn.f32x2 %0, %1, %2, %3;" : "=l"(d) : "l"(a), "l"(b), "l"(c));
    return d;
}
__device__ __forceinline__ ull pk2(float x, float y) {
    ull r;
    asm("mov.b64 %0, {%1, %2};" : "=l"(r) : "f"(x), "f"(y));
    return r;
}
__device__ __forceinline__ void upk2(ull v, float &x, float &y) {
    asm("mov.b64 {%0, %1}, %2;" : "=f"(x), "=f"(y) : "l"(v));
}

// stable softplus
__device__ __forceinline__ float sp_(float x) {
    return fmaxf(x, 0.f) + __logf(1.f + __expf(-fabsf(x)));
}
// HW tanh approx (single MUFU)
__device__ __forceinline__ float tanh_(float x) {
    float y;
    asm("tanh.approx.f32 %0, %1;" : "=f"(y) : "f"(x));
    return y;
}

// cubic Hermite derivative: dX = m0 + (diff-m0)*f*(4-3f)
__device__ __forceinline__ float spline_eval(const float* __restrict__ xrow, float t) {
    int idx = (int)t;
    idx = min(idx, L - 2);
    float f = t - (float)idx;
    const float* p = xrow + idx * C;
    float x0 = __ldg(p);
    float x1 = __ldg(p + C);
    float diff = x1 - x0;
    float m0 = diff;
    if (idx > 0) m0 = x0 - __ldg(p - C);
    return fmaf((diff - m0) * f, fmaf(-3.f, f, 4.f), m0);
}

__global__ __launch_bounds__(128, 2)
void cde_kernel(const float* __restrict__ X,      // (4096,64,7)
                const float* __restrict__ Winit,  // (32,7)
                const float* __restrict__ binit,  // (32)
                const float* __restrict__ Wf1,    // (32,32)
                const float* __restrict__ bf1,    // (32)
                const float* __restrict__ Wf2,    // (224,32)
                const float* __restrict__ bf2,    // (224)
                const float* __restrict__ Wo1,    // (16,32)
                const float* __restrict__ bo1,    // (16)
                const float* __restrict__ Wo2,    // (3,16)
                const float* __restrict__ bo2,    // (3)
                float* __restrict__ out)          // (4096,3)
{
    // 4 warps = 2 pairs; pair serves 7 batches (+1 dummy slot); A: c0-3, B: c4-7(pad)
    __shared__ __align__(16) float sZ[2][8][32];      // 2 KB
    __shared__ __align__(16) float sH1[2][8][32];     // 2 KB
    __shared__ __align__(16) float sDX[2][3][8][8];   // 1.5 KB
    __shared__ __align__(16) float sPart[4][8][32];   // 4 KB

    const int tid  = threadIdx.x;
    const int w    = tid >> 5;
    const int lane = tid & 31;          // = h
    const int pair = w >> 1;
    const int isB  = w & 1;
    const int partner = w ^ 1;
    const int gpair = blockIdx.x * 2 + pair;
    const int pairbase = gpair * NBPAIR;
    const int ownbase  = pairbase + isB * 4;     // A owns 4 (bs 0-3), B owns 3 (bs 4-6)
    const int nk = isB ? 3 : 4;

    // ---- Wf2 own c-half, j-pair packed, in registers ----
    ull wreg[4][16];
    float b2[4];
#pragma unroll
    for (int cp = 0; cp < 4; cp++) {
        int cg = isB * 4 + cp;
        if (cg < C) {
            const float2* wp = reinterpret_cast<const float2*>(Wf2 + (lane * C + cg) * 32);
#pragma unroll
            for (int jp = 0; jp < 16; jp++) { float2 v = __ldg(wp + jp); wreg[cp][jp] = pk2(v.x, v.y); }
            b2[cp] = __ldg(bf2 + lane * C + cg);
        } else {
#pragma unroll
            for (int jp = 0; jp < 16; jp++) wreg[cp][jp] = 0ull;
            b2[cp] = 0.f;
        }
    }
    ull rw1[16];
    {
        const float2* p1 = reinterpret_cast<const float2*>(Wf1 + lane * 32);
#pragma unroll
        for (int jp = 0; jp < 16; jp++) { float2 v = __ldg(p1 + jp); rw1[jp] = pk2(v.x, v.y); }
    }
    const float rbf1 = __ldg(bf1 + lane);

    // dX mapping: lane -> (db 0..3, dc 0..7); B's db=3 -> dummy slot 7
    const int db = lane >> 3;
    const int dc = lane & 7;
    const int sbatch = min(ownbase + db, 4095);  // clamped for dummies
    const float* xrow = X + (size_t)sbatch * (L * C) + ((dc < C) ? dc : 0);

    // z0 for own (clamped) batches — dummy entries finite
    float z[4];
#pragma unroll
    for (int k = 0; k < 4; k++) {
        int gb = min(ownbase + k, 4095);
        float acc = __ldg(binit + lane);
        const float* xp = X + (size_t)gb * (L * C);
#pragma unroll
        for (int c = 0; c < C; c++) acc = fmaf(__ldg(xp + c), __ldg(Winit + lane * C + c), acc);
        z[k] = acc;
    }

    // initial dX(t=0) -> slot 0
    {
        float v = 0.f;
        if (dc < C) v = __ldg(xrow + C) - __ldg(xrow);
        sDX[pair][0][isB * 4 + db][dc] = v;
    }

    float t0 = 0.f;
#pragma unroll 1
    for (int i = 0; i < NSTEPS; i++, t0 += 0.5f) {
        // spline: t0+0.25 -> slot 2 ; t0+0.5 -> slot (i+1)&1
        {
            float vb = 0.f, vc = 0.f;
            if (dc < C) {
                vb = spline_eval(xrow, t0 + 0.25f);
                vc = spline_eval(xrow, t0 + 0.5f);
            }
            sDX[pair][2][isB * 4 + db][dc] = vb;
            sDX[pair][(i + 1) & 1][isB * 4 + db][dc] = vc;
        }
        const int slotA = i & 1, slotC = (i + 1) & 1;

        float zs[4], ksum[4];
#pragma unroll
        for (int k = 0; k < 4; k++) { zs[k] = z[k]; ksum[k] = 0.f; }

#pragma unroll 1
        for (int s = 0; s < 4; s++) {
            const int slot = (s == 0) ? slotA : ((s == 3) ? slotC : 2);

            // own zs -> sZ (B's k=3 goes to dummy slot 7)
            __syncwarp();
#pragma unroll
            for (int k = 0; k < 4; k++) sZ[pair][isB * 4 + k][lane] = zs[k];
            __syncwarp();

            // mm1: 4 interleaved accumulator chains, fully unrolled
            ull a1[4];
#pragma unroll
            for (int k = 0; k < 4; k++) a1[k] = 0ull;
#pragma unroll
            for (int q = 0; q < 8; q++) {
#pragma unroll
                for (int k = 0; k < 4; k++) {
                    ulonglong2 zq = *reinterpret_cast<const ulonglong2*>(&sZ[pair][isB * 4 + k][4 * q]);
                    a1[k] = ffma2(zq.x, rw1[2 * q], a1[k]);
                    a1[k] = ffma2(zq.y, rw1[2 * q + 1], a1[k]);
                }
            }
            // interleaved softplus x4
            float pre[4];
#pragma unroll
            for (int k = 0; k < 4; k++) { float u, v; upk2(a1[k], u, v); pre[k] = u + v + rbf1; }
#pragma unroll
            for (int k = 0; k < 4; k++) sH1[pair][isB * 4 + k][lane] = sp_(pre[k]);
            asm volatile("bar.sync %0, 64;" :: "r"(pair + 1) : "memory");

            // mm2 for the pair's 7 batches (own c-half, weights in regs)
#pragma unroll 1
            for (int bs = 0; bs < NBPAIR; bs++) {
                ulonglong2 dxp = *reinterpret_cast<const ulonglong2*>(&sDX[pair][slot][bs][isB * 4]);
                ull h1p[16];
                const ulonglong2* hp = reinterpret_cast<const ulonglong2*>(&sH1[pair][bs][0]);
#pragma unroll
                for (int q = 0; q < 8; q++) { ulonglong2 v = hp[q]; h1p[2 * q] = v.x; h1p[2 * q + 1] = v.y; }
                ull acc0 = 0ull, acc1 = 0ull, acc2 = 0ull, acc3 = 0ull;
#pragma unroll
                for (int jp = 0; jp < 16; jp++) {
                    acc0 = ffma2(h1p[jp], wreg[0][jp], acc0);
                    acc1 = ffma2(h1p[jp], wreg[1][jp], acc1);
                    acc2 = ffma2(h1p[jp], wreg[2][jp], acc2);
                    acc3 = ffma2(h1p[jp], wreg[3][jp], acc3);
                }
                float u, v, g0, g1, g2, g3;
                upk2(acc0, u, v); g0 = tanh_(u + v + b2[0]);
                upk2(acc1, u, v); g1 = tanh_(u + v + b2[1]);
                upk2(acc2, u, v); g2 = tanh_(u + v + b2[2]);
                upk2(acc3, u, v); g3 = tanh_(u + v + b2[3]);
                ull e = ffma2(pk2(g0, g1), dxp.x, ffma2(pk2(g2, g3), dxp.y, 0ull));
                float e0, e1; upk2(e, e0, e1);
                sPart[w][bs][lane] = e0 + e1;
            }
            asm volatile("bar.sync %0, 64;" :: "r"(pair + 1) : "memory");

            // combine partials for own real batches; RK4 bookkeeping
            const float wk = (s == 1 || s == 2) ? 2.f : 1.f;
            const float an = (s < 2) ? 0.25f : 0.5f;
#pragma unroll
            for (int k = 0; k < 4; k++) {
                if (k < nk) {
                    int bs = isB * 4 + k;
                    float kk = sPart[w][bs][lane] + sPart[partner][bs][lane];
                    ksum[k] = fmaf(wk, kk, ksum[k]);
                    zs[k]   = fmaf(an, kk, z[k]);
                }
            }
        }
#pragma unroll
        for (int k = 0; k < 4; k++) z[k] = fmaf(ksum[k], (1.f / 12.f), z[k]);  // h/6
    }

    // partner must finish reading sPart/sH1 before scratch reuse
    asm volatile("bar.sync %0, 64;" :: "r"(pair + 1) : "memory");

    // output head (own real batches)
#pragma unroll
    for (int k = 0; k < 4; k++) sZ[pair][isB * 4 + k][lane] = z[k];
    __syncwarp();
    float* so = &sPart[w][0][0];   // [4][32] scratch, own-warp only
    if (lane < 16) {
#pragma unroll
        for (int k = 0; k < 4; k++) {
            float acc = __ldg(bo1 + lane);
#pragma unroll
            for (int hh = 0; hh < 32; hh++)
                acc = fmaf(sZ[pair][isB * 4 + k][hh], __ldg(Wo1 + lane * 32 + hh), acc);
            so[k * 32 + lane] = sp_(acc);
        }
    }
    __syncwarp();
    if (lane < 12) {
        int k = lane >> 2;            // 0..2 (only need k<3 here? no: 12 lanes = 4 k x 3 jo)
        int jo = lane & 3;
    }
    // 4 k x 3 outputs = 12 work items
    if (lane < 12) {
        int k = lane / 3;
        int jo = lane - 3 * k;
        int gb = ownbase + k;
        if (k < nk && gb < 4096) {
            float acc = __ldg(bo2 + jo);
#pragma unroll
            for (int i2 = 0; i2 < 16; i2++)
                acc = fmaf(so[k * 32 + i2], __ldg(Wo2 + jo * 16 + i2), acc);
            out[(size_t)gb * 3 + jo] = acc;
        }
    }
}

extern "C" void kernel_launch(void* const* d_in, const int* in_sizes, int n_in,
                              void* d_out, int out_size) {
    const float* X     = (const float*)d_in[0];
    const float* Winit = (const float*)d_in[1];
    const float* binit = (const float*)d_in[2];
    const float* Wf1   = (const float*)d_in[3];
    const float* bf1   = (const float*)d_in[4];
    const float* Wf2   = (const float*)d_in[5];
    const float* bf2   = (const float*)d_in[6];
    const float* Wo1   = (const float*)d_in[7];
    const float* bo1   = (const float*)d_in[8];
    const float* Wo2   = (const float*)d_in[9];
    const float* bo2   = (const float*)d_in[10];
    float* out = (float*)d_out;

    // 293 CTAs x 128 thr: 2 pairs/CTA x 7 batches = 4102 slots >= 4096 (tail guarded)
    cde_kernel<<<NCTA, 128>>>(X, Winit, binit, Wf1, bf1, Wf2, bf2,
                              Wo1, bo1, Wo2, bo2, out);
}